// round 3
// baseline (speedup 1.0000x reference)
#include <cuda_runtime.h>
#include <math.h>

// StatisticalFeatureExtractor: (B=64, C=16, T=65536) fp32 -> (B, C, 17) fp32
// One CTA per (b,c) row. Two passes over the row:
//   pass 1 (HBM): sum x, sum x^2, sum |x|, sum sqrt(|x|), min, max, zero-cross count
//   pass 2 (L2-resident re-read): centered d^2, d^3, d^4 sums + mean-cross count
// Final 17 features computed in double by thread 0.

#define TLEN    65536
#define CHUNKS  (TLEN / 4)
#define THREADS 1024
#define NWARP   (THREADS / 32)
#define EPSV    1e-8

__device__ __forceinline__ float sqrt_approx(float v) {
    float r;
    asm("sqrt.approx.f32 %0, %1;" : "=f"(r) : "f"(v));
    return r;
}

__device__ __forceinline__ int signf(float v) {
    return (v > 0.0f) - (v < 0.0f);
}

__device__ __forceinline__ float warp_sum(float v) {
#pragma unroll
    for (int o = 16; o; o >>= 1) v += __shfl_xor_sync(0xffffffffu, v, o);
    return v;
}
__device__ __forceinline__ int warp_sumi(int v) {
#pragma unroll
    for (int o = 16; o; o >>= 1) v += __shfl_xor_sync(0xffffffffu, v, o);
    return v;
}
__device__ __forceinline__ float warp_max(float v) {
#pragma unroll
    for (int o = 16; o; o >>= 1) v = fmaxf(v, __shfl_xor_sync(0xffffffffu, v, o));
    return v;
}
__device__ __forceinline__ float warp_min(float v) {
#pragma unroll
    for (int o = 16; o; o >>= 1) v = fminf(v, __shfl_xor_sync(0xffffffffu, v, o));
    return v;
}

__global__ __launch_bounds__(THREADS, 1)
void stat_feat_kernel(const float* __restrict__ x, float* __restrict__ out) {
    const int row = blockIdx.x;
    const float* __restrict__ xr = x + (size_t)row * TLEN;
    const float4* __restrict__ x4 = reinterpret_cast<const float4*>(xr);

    const int tid  = threadIdx.x;
    const int wid  = tid >> 5;
    const int lane = tid & 31;

    __shared__ float w_a[NWARP], w_b[NWARP], w_c[NWARP], w_d[NWARP];
    __shared__ float w_mx[NWARP], w_mn[NWARP];
    __shared__ int   w_i[NWARP];
    __shared__ float s_mean;
    __shared__ float s_res[8];   // [S1, S2, Sabs, Ssqrt, max, min] broadcast to t0's regs already; kept for pass2 handoff
    __shared__ int   s_zc;

    // ---------------- pass 1: raw sums over HBM stream ----------------
    float s1 = 0.f, s2 = 0.f, sa = 0.f, sq = 0.f;
    float mx = -INFINITY, mn = INFINITY;
    int zc = 0;

#pragma unroll 4
    for (int k = tid; k < CHUNKS; k += THREADS) {
        float4 v = x4[k];
        // element following this chunk (first element of next chunk); for the
        // final chunk of the row, duplicate v.w so the 4th pair contributes 0.
        float nxt = (k != CHUNKS - 1) ? __ldg(xr + 4 * k + 4) : v.w;
        float a0 = v.x, a1 = v.y, a2 = v.z, a3 = v.w;

        s1 += (a0 + a1) + (a2 + a3);
        s2 = fmaf(a0, a0, s2); s2 = fmaf(a1, a1, s2);
        s2 = fmaf(a2, a2, s2); s2 = fmaf(a3, a3, s2);
        float b0 = fabsf(a0), b1 = fabsf(a1), b2 = fabsf(a2), b3 = fabsf(a3);
        sa += (b0 + b1) + (b2 + b3);
        sq += (sqrt_approx(b0) + sqrt_approx(b1)) + (sqrt_approx(b2) + sqrt_approx(b3));
        mx = fmaxf(mx, fmaxf(fmaxf(a0, a1), fmaxf(a2, a3)));
        mn = fminf(mn, fminf(fminf(a0, a1), fminf(a2, a3)));

        int g0 = signf(a0), g1 = signf(a1), g2 = signf(a2), g3 = signf(a3), g4 = signf(nxt);
        zc += (g0 != g1) + (g1 != g2) + (g2 != g3) + (g3 != g4);
    }

    // block reduce (warp shuffle + one smem round)
    s1 = warp_sum(s1); s2 = warp_sum(s2); sa = warp_sum(sa); sq = warp_sum(sq);
    mx = warp_max(mx); mn = warp_min(mn); zc = warp_sumi(zc);
    if (lane == 0) {
        w_a[wid] = s1; w_b[wid] = s2; w_c[wid] = sa; w_d[wid] = sq;
        w_mx[wid] = mx; w_mn[wid] = mn; w_i[wid] = zc;
    }
    __syncthreads();
    if (wid == 0) {
        float r1 = w_a[lane], r2 = w_b[lane], r3 = w_c[lane], r4 = w_d[lane];
        float rmx = w_mx[lane], rmn = w_mn[lane];
        int rzc = w_i[lane];
        r1 = warp_sum(r1); r2 = warp_sum(r2); r3 = warp_sum(r3); r4 = warp_sum(r4);
        rmx = warp_max(rmx); rmn = warp_min(rmn); rzc = warp_sumi(rzc);
        if (lane == 0) {
            s_res[0] = r1; s_res[1] = r2; s_res[2] = r3; s_res[3] = r4;
            s_res[4] = rmx; s_res[5] = rmn;
            s_zc = rzc;
            s_mean = (float)((double)r1 * (1.0 / (double)TLEN));
        }
    }
    __syncthreads();

    const float mean = s_mean;

    // ---------------- pass 2: centered moments + mean crossings (L2 re-read) ----------------
    float d2 = 0.f, d3 = 0.f, d4 = 0.f;
    int mc = 0;

#pragma unroll 4
    for (int k = tid; k < CHUNKS; k += THREADS) {
        float4 v = x4[k];
        float nxt = (k != CHUNKS - 1) ? __ldg(xr + 4 * k + 4) : v.w;
        float a0 = v.x - mean, a1 = v.y - mean, a2 = v.z - mean, a3 = v.w - mean;
        float an = nxt - mean;

        float t0 = a0 * a0, t1 = a1 * a1, t2 = a2 * a2, t3 = a3 * a3;
        d2 += (t0 + t1) + (t2 + t3);
        d3 = fmaf(t0, a0, d3); d3 = fmaf(t1, a1, d3);
        d3 = fmaf(t2, a2, d3); d3 = fmaf(t3, a3, d3);
        d4 = fmaf(t0, t0, d4); d4 = fmaf(t1, t1, d4);
        d4 = fmaf(t2, t2, d4); d4 = fmaf(t3, t3, d4);

        int g0 = signf(a0), g1 = signf(a1), g2 = signf(a2), g3 = signf(a3), g4 = signf(an);
        mc += (g0 != g1) + (g1 != g2) + (g2 != g3) + (g3 != g4);
    }

    d2 = warp_sum(d2); d3 = warp_sum(d3); d4 = warp_sum(d4); mc = warp_sumi(mc);
    if (lane == 0) {
        w_a[wid] = d2; w_b[wid] = d3; w_c[wid] = d4; w_i[wid] = mc;
    }
    __syncthreads();

    if (tid == 0) {
        float rd2 = 0.f, rd3 = 0.f, rd4 = 0.f;
        int rmc = 0;
        // 32 partials: serial double accumulation on thread 0 (tiny cost, best accuracy)
        double D2 = 0.0, D3 = 0.0, D4 = 0.0;
        for (int i = 0; i < NWARP; i++) {
            D2 += (double)w_a[i]; D3 += (double)w_b[i]; D4 += (double)w_c[i];
            rmc += w_i[i];
        }
        (void)rd2; (void)rd3; (void)rd4;

        const double Td   = (double)TLEN;
        const double invT = 1.0 / Td;
        double S1 = s_res[0], S2 = s_res[1], Sa = s_res[2], Sq = s_res[3];
        double pk = s_res[4], pkn = s_res[5];
        int    zct = s_zc;

        double meanv     = S1 * invT;
        double var       = D2 / (Td - 1.0);
        double stdv      = sqrt(var);
        double sq_mean   = S2 * invT;
        double rms       = sqrt(sq_mean);
        double ptp       = pk - pkn;
        double abs_peak  = fabs(pk);
        double crest     = abs_peak / (rms + EPSV);
        double mean_abs  = Sa * invT;
        double shape     = rms / (mean_abs + EPSV);
        double impulse   = abs_peak / (mean_abs + EPSV);
        double sqrt_mean = Sq * invT;
        double clearance = abs_peak / (sqrt_mean * sqrt_mean + EPSV);
        double skew      = (D3 * invT) / (stdv * stdv * stdv + EPSV);
        double kurt      = (D4 * invT) / (var * var + EPSV) - 3.0;
        double zcr       = (double)zct / (Td - 1.0);
        double mcr       = (double)rmc / (Td - 1.0);
        double margin    = abs_peak / (sqrt_mean + EPSV);
        double energy    = S2;

        float* o = out + (size_t)row * 17;
        o[0]  = (float)meanv;
        o[1]  = (float)stdv;
        o[2]  = (float)var;
        o[3]  = (float)rms;
        o[4]  = (float)pk;
        o[5]  = (float)pkn;
        o[6]  = (float)ptp;
        o[7]  = (float)crest;
        o[8]  = (float)shape;
        o[9]  = (float)impulse;
        o[10] = (float)clearance;
        o[11] = (float)skew;
        o[12] = (float)kurt;
        o[13] = (float)zcr;
        o[14] = (float)mcr;
        o[15] = (float)margin;
        o[16] = (float)energy;
    }
}

extern "C" void kernel_launch(void* const* d_in, const int* in_sizes, int n_in,
                              void* d_out, int out_size) {
    const float* x = (const float*)d_in[0];
    float* out = (float*)d_out;
    int rows = in_sizes[0] / TLEN;   // 64*16 = 1024
    stat_feat_kernel<<<rows, THREADS>>>(x, out);
}

// round 4
// speedup vs baseline: 1.0149x; 1.0149x over previous
#include <cuda_runtime.h>
#include <math.h>

// StatisticalFeatureExtractor: (B=64, C=16, T=65536) fp32 -> (B, C, 17) fp32
// One CTA (512 thr) per row, 2 CTAs/SM. Two passes (pass 2 L2-resident):
//   pass 1: sum x, sum x^2, sum|x|, sum sqrt|x|, min, max, zero-crossings
//   pass 2: centered d^2,d^3,d^4 + mean-crossings
// Packed f32x2 accumulators; crossings via signbit XOR + warp ballot.

#define TLEN    65536
#define CHUNKS  (TLEN / 4)
#define THREADS 512
#define NWARP   (THREADS / 32)
#define EPSV    1e-8

typedef unsigned long long u64;

__device__ __forceinline__ u64 pk2(float x, float y) {
    u64 r; asm("mov.b64 %0, {%1, %2};" : "=l"(r) : "f"(x), "f"(y)); return r;
}
__device__ __forceinline__ void up2(u64 a, float& x, float& y) {
    asm("mov.b64 {%0, %1}, %2;" : "=f"(x), "=f"(y) : "l"(a));
}
__device__ __forceinline__ u64 add2(u64 a, u64 b) {
    u64 r; asm("add.rn.f32x2 %0, %1, %2;" : "=l"(r) : "l"(a), "l"(b)); return r;
}
__device__ __forceinline__ u64 mul2(u64 a, u64 b) {
    u64 r; asm("mul.rn.f32x2 %0, %1, %2;" : "=l"(r) : "l"(a), "l"(b)); return r;
}
__device__ __forceinline__ u64 fma2(u64 a, u64 b, u64 c) {
    u64 r; asm("fma.rn.f32x2 %0, %1, %2, %3;" : "=l"(r) : "l"(a), "l"(b), "l"(c)); return r;
}
__device__ __forceinline__ float sqrt_approx(float v) {
    float r; asm("sqrt.approx.f32 %0, %1;" : "=f"(r) : "f"(v)); return r;
}
__device__ __forceinline__ float hsum2(u64 a) { float x, y; up2(a, x, y); return x + y; }

__device__ __forceinline__ float warp_sum(float v) {
#pragma unroll
    for (int o = 16; o; o >>= 1) v += __shfl_xor_sync(0xffffffffu, v, o);
    return v;
}
__device__ __forceinline__ int warp_sumi(int v) {
#pragma unroll
    for (int o = 16; o; o >>= 1) v += __shfl_xor_sync(0xffffffffu, v, o);
    return v;
}
__device__ __forceinline__ float warp_max(float v) {
#pragma unroll
    for (int o = 16; o; o >>= 1) v = fmaxf(v, __shfl_xor_sync(0xffffffffu, v, o));
    return v;
}
__device__ __forceinline__ float warp_min(float v) {
#pragma unroll
    for (int o = 16; o; o >>= 1) v = fminf(v, __shfl_xor_sync(0xffffffffu, v, o));
    return v;
}

__global__ __launch_bounds__(THREADS, 2)
void stat_feat_kernel(const float* __restrict__ x, float* __restrict__ out) {
    const int row = blockIdx.x;
    const float* __restrict__ xr = x + (size_t)row * TLEN;
    const float4* __restrict__ x4 = reinterpret_cast<const float4*>(xr);

    const int tid  = threadIdx.x;
    const int wid  = tid >> 5;
    const int lane = tid & 31;

    __shared__ float w_a[NWARP], w_b[NWARP], w_c[NWARP], w_d[NWARP];
    __shared__ float w_mx[NWARP], w_mn[NWARP];
    __shared__ int   w_i[NWARP];
    __shared__ float s_mean;
    __shared__ float s_res[6];
    __shared__ int   s_zc;

    const u64 ABSM = 0x7fffffff7fffffffULL;

    // ---------------- pass 1: raw sums (HBM stream) ----------------
    u64 s1p = 0, s2p = 0, sap = 0;
    float sq = 0.f;
    float mx = -INFINITY, mn = INFINITY;
    int zc = 0;

#pragma unroll 4
    for (int k = tid; k < CHUNKS; k += THREADS) {
        float4 v = x4[k];
        u64 plo = pk2(v.x, v.y), phi = pk2(v.z, v.w);

        s1p = add2(s1p, add2(plo, phi));
        s2p = fma2(plo, plo, s2p);
        s2p = fma2(phi, phi, s2p);

        u64 alo = plo & ABSM, ahi = phi & ABSM;
        sap = add2(sap, add2(alo, ahi));

        float b0, b1, b2, b3;
        up2(alo, b0, b1); up2(ahi, b2, b3);
        sq += (sqrt_approx(b0) + sqrt_approx(b1)) + (sqrt_approx(b2) + sqrt_approx(b3));

        mx = fmaxf(mx, fmaxf(fmaxf(v.x, v.y), fmaxf(v.z, v.w)));
        mn = fminf(mn, fminf(fminf(v.x, v.y), fminf(v.z, v.w)));

        int u0 = __float_as_int(v.x), u1 = __float_as_int(v.y);
        int u2 = __float_as_int(v.z), u3 = __float_as_int(v.w);
        zc += (int)(((unsigned)(u0 ^ u1)) >> 31)
            + (int)(((unsigned)(u1 ^ u2)) >> 31)
            + (int)(((unsigned)(u2 ^ u3)) >> 31);

        // cross-chunk pairs: lanes 0..30 via ballot (counted once on lane 0)
        unsigned bf = __ballot_sync(0xffffffffu, u0 < 0);
        unsigned bl = __ballot_sync(0xffffffffu, u3 < 0);
        if (lane == 0) zc += __popc((bl ^ (bf >> 1)) & 0x7fffffffu);
        // lane 31's successor chunk lives in the next warp / next iter
        if (lane == 31) {
            float nxt = (k == CHUNKS - 1) ? v.w : __ldg(xr + 4 * k + 4);
            zc += (int)(((unsigned)(u3 ^ __float_as_int(nxt))) >> 31);
        }
    }

    float s1 = hsum2(s1p), s2 = hsum2(s2p), sa = hsum2(sap);

    s1 = warp_sum(s1); s2 = warp_sum(s2); sa = warp_sum(sa); sq = warp_sum(sq);
    mx = warp_max(mx); mn = warp_min(mn); zc = warp_sumi(zc);
    if (lane == 0) {
        w_a[wid] = s1; w_b[wid] = s2; w_c[wid] = sa; w_d[wid] = sq;
        w_mx[wid] = mx; w_mn[wid] = mn; w_i[wid] = zc;
    }
    __syncthreads();
    if (wid == 0) {
        bool ok = lane < NWARP;
        float r1 = ok ? w_a[lane] : 0.f, r2 = ok ? w_b[lane] : 0.f;
        float r3 = ok ? w_c[lane] : 0.f, r4 = ok ? w_d[lane] : 0.f;
        float rmx = ok ? w_mx[lane] : -INFINITY, rmn = ok ? w_mn[lane] : INFINITY;
        int rzc = ok ? w_i[lane] : 0;
        r1 = warp_sum(r1); r2 = warp_sum(r2); r3 = warp_sum(r3); r4 = warp_sum(r4);
        rmx = warp_max(rmx); rmn = warp_min(rmn); rzc = warp_sumi(rzc);
        if (lane == 0) {
            s_res[0] = r1; s_res[1] = r2; s_res[2] = r3; s_res[3] = r4;
            s_res[4] = rmx; s_res[5] = rmn;
            s_zc = rzc;
            s_mean = (float)((double)r1 * (1.0 / (double)TLEN));
        }
    }
    __syncthreads();

    const float mean = s_mean;
    const u64 nm2 = pk2(-mean, -mean);

    // ---------------- pass 2: centered moments + mean crossings (L2 re-read) ----------------
    u64 d2p = 0, d3p = 0, d4p = 0;
    int mc = 0;

#pragma unroll 4
    for (int k = tid; k < CHUNKS; k += THREADS) {
        float4 v = x4[k];
        u64 plo = pk2(v.x, v.y), phi = pk2(v.z, v.w);
        u64 dlo = add2(plo, nm2), dhi = add2(phi, nm2);
        u64 tlo = mul2(dlo, dlo), thi = mul2(dhi, dhi);

        d2p = add2(d2p, add2(tlo, thi));
        d3p = fma2(tlo, dlo, d3p);
        d3p = fma2(thi, dhi, d3p);
        d4p = fma2(tlo, tlo, d4p);
        d4p = fma2(thi, thi, d4p);

        float d0, d1, d2v, d3v;
        up2(dlo, d0, d1); up2(dhi, d2v, d3v);
        int u0 = __float_as_int(d0), u1 = __float_as_int(d1);
        int u2 = __float_as_int(d2v), u3 = __float_as_int(d3v);
        mc += (int)(((unsigned)(u0 ^ u1)) >> 31)
            + (int)(((unsigned)(u1 ^ u2)) >> 31)
            + (int)(((unsigned)(u2 ^ u3)) >> 31);

        unsigned bf = __ballot_sync(0xffffffffu, u0 < 0);
        unsigned bl = __ballot_sync(0xffffffffu, u3 < 0);
        if (lane == 0) mc += __popc((bl ^ (bf >> 1)) & 0x7fffffffu);
        if (lane == 31) {
            float nxtc = (k == CHUNKS - 1) ? d3v : (__ldg(xr + 4 * k + 4) - mean);
            mc += (int)(((unsigned)(u3 ^ __float_as_int(nxtc))) >> 31);
        }
    }

    float d2 = hsum2(d2p), d3 = hsum2(d3p), d4 = hsum2(d4p);
    d2 = warp_sum(d2); d3 = warp_sum(d3); d4 = warp_sum(d4); mc = warp_sumi(mc);
    if (lane == 0) { w_a[wid] = d2; w_b[wid] = d3; w_c[wid] = d4; w_i[wid] = mc; }
    __syncthreads();

    if (tid == 0) {
        double D2 = 0.0, D3 = 0.0, D4 = 0.0;
        int rmc = 0;
        for (int i = 0; i < NWARP; i++) {
            D2 += (double)w_a[i]; D3 += (double)w_b[i]; D4 += (double)w_c[i];
            rmc += w_i[i];
        }

        const double Td   = (double)TLEN;
        const double invT = 1.0 / Td;
        double S1 = s_res[0], S2 = s_res[1], Sa = s_res[2], Sq = s_res[3];
        double pk = s_res[4], pkn = s_res[5];
        int    zct = s_zc;

        double meanv     = S1 * invT;
        double var       = D2 / (Td - 1.0);
        double stdv      = sqrt(var);
        double sq_mean   = S2 * invT;
        double rms       = sqrt(sq_mean);
        double ptp       = pk - pkn;
        double abs_peak  = fabs(pk);
        double crest     = abs_peak / (rms + EPSV);
        double mean_abs  = Sa * invT;
        double shape     = rms / (mean_abs + EPSV);
        double impulse   = abs_peak / (mean_abs + EPSV);
        double sqrt_mean = Sq * invT;
        double clearance = abs_peak / (sqrt_mean * sqrt_mean + EPSV);
        double skew      = (D3 * invT) / (stdv * stdv * stdv + EPSV);
        double kurt      = (D4 * invT) / (var * var + EPSV) - 3.0;
        double zcr       = (double)zct / (Td - 1.0);
        double mcr       = (double)rmc / (Td - 1.0);
        double margin    = abs_peak / (sqrt_mean + EPSV);
        double energy    = S2;

        float* o = out + (size_t)row * 17;
        o[0]  = (float)meanv;
        o[1]  = (float)stdv;
        o[2]  = (float)var;
        o[3]  = (float)rms;
        o[4]  = (float)pk;
        o[5]  = (float)pkn;
        o[6]  = (float)ptp;
        o[7]  = (float)crest;
        o[8]  = (float)shape;
        o[9]  = (float)impulse;
        o[10] = (float)clearance;
        o[11] = (float)skew;
        o[12] = (float)kurt;
        o[13] = (float)zcr;
        o[14] = (float)mcr;
        o[15] = (float)margin;
        o[16] = (float)energy;
    }
}

extern "C" void kernel_launch(void* const* d_in, const int* in_sizes, int n_in,
                              void* d_out, int out_size) {
    const float* x = (const float*)d_in[0];
    float* out = (float*)d_out;
    int rows = in_sizes[0] / TLEN;   // 64*16 = 1024
    stat_feat_kernel<<<rows, THREADS>>>(x, out);
}

// round 8
// speedup vs baseline: 1.8263x; 1.7995x over previous
#include <cuda_runtime.h>
#include <math.h>

// StatisticalFeatureExtractor: (B=64, C=16, T=65536) fp32 -> (B, C, 17) fp32
// One CTA (512 thr) per row. Two passes (pass 2 L2-resident).
// Hot loops fully branch-free (no ballots, no divergent loads, no selects);
// cross-chunk sign pairs via shfl_down; warp-span boundary pairs in cleanup.
// unroll 8 for MLP=8 load batching.

#define TLEN    65536
#define CHUNKS  (TLEN / 4)
#define THREADS 512
#define NWARP   (THREADS / 32)
#define EPSV    1e-8

typedef unsigned long long u64;

__device__ __forceinline__ u64 pk2(float x, float y) {
    u64 r; asm("mov.b64 %0, {%1, %2};" : "=l"(r) : "f"(x), "f"(y)); return r;
}
__device__ __forceinline__ void up2(u64 a, float& x, float& y) {
    asm("mov.b64 {%0, %1}, %2;" : "=f"(x), "=f"(y) : "l"(a));
}
__device__ __forceinline__ u64 add2(u64 a, u64 b) {
    u64 r; asm("add.rn.f32x2 %0, %1, %2;" : "=l"(r) : "l"(a), "l"(b)); return r;
}
__device__ __forceinline__ u64 mul2(u64 a, u64 b) {
    u64 r; asm("mul.rn.f32x2 %0, %1, %2;" : "=l"(r) : "l"(a), "l"(b)); return r;
}
__device__ __forceinline__ u64 fma2(u64 a, u64 b, u64 c) {
    u64 r; asm("fma.rn.f32x2 %0, %1, %2, %3;" : "=l"(r) : "l"(a), "l"(b), "l"(c)); return r;
}
__device__ __forceinline__ float sqrt_approx(float v) {
    float r; asm("sqrt.approx.f32 %0, %1;" : "=f"(r) : "f"(v)); return r;
}
__device__ __forceinline__ float hsum2(u64 a) { float x, y; up2(a, x, y); return x + y; }

__device__ __forceinline__ float warp_sum(float v) {
#pragma unroll
    for (int o = 16; o; o >>= 1) v += __shfl_xor_sync(0xffffffffu, v, o);
    return v;
}
__device__ __forceinline__ int warp_sumi(int v) {
#pragma unroll
    for (int o = 16; o; o >>= 1) v += __shfl_xor_sync(0xffffffffu, v, o);
    return v;
}
__device__ __forceinline__ float warp_max(float v) {
#pragma unroll
    for (int o = 16; o; o >>= 1) v = fmaxf(v, __shfl_xor_sync(0xffffffffu, v, o));
    return v;
}
__device__ __forceinline__ float warp_min(float v) {
#pragma unroll
    for (int o = 16; o; o >>= 1) v = fminf(v, __shfl_xor_sync(0xffffffffu, v, o));
    return v;
}

__global__ __launch_bounds__(THREADS, 2)
void stat_feat_kernel(const float* __restrict__ x, float* __restrict__ out) {
    const int row = blockIdx.x;
    const float* __restrict__ xr = x + (size_t)row * TLEN;
    const float4* __restrict__ x4 = reinterpret_cast<const float4*>(xr);

    const int tid  = threadIdx.x;
    const int wid  = tid >> 5;
    const int lane = tid & 31;
    const unsigned vmask = (lane != 31) ? 1u : 0u;   // gate for shfl-derived pair

    __shared__ float w_a[NWARP], w_b[NWARP], w_c[NWARP], w_d[NWARP];
    __shared__ float w_mx[NWARP], w_mn[NWARP];
    __shared__ int   w_i[NWARP], w_j[NWARP];
    __shared__ float s_mean;
    __shared__ float s_res[6];
    __shared__ int   s_zc;

    const u64 ABSM = 0x7fffffff7fffffffULL;

    // ---------------- pass 1: raw sums (HBM stream), branch-free ----------------
    u64 s1p = 0, s2p = 0, sap = 0;
    float sq = 0.f;
    float mx = -INFINITY, mn = INFINITY;
    int zc = 0;

#pragma unroll 8
    for (int k = tid; k < CHUNKS; k += THREADS) {
        float4 v = x4[k];
        u64 plo = pk2(v.x, v.y), phi = pk2(v.z, v.w);

        s1p = add2(s1p, add2(plo, phi));
        s2p = fma2(plo, plo, s2p);
        s2p = fma2(phi, phi, s2p);

        u64 alo = plo & ABSM, ahi = phi & ABSM;
        sap = add2(sap, add2(alo, ahi));

        float b0, b1, b2, b3;
        up2(alo, b0, b1); up2(ahi, b2, b3);
        sq += (sqrt_approx(b0) + sqrt_approx(b1)) + (sqrt_approx(b2) + sqrt_approx(b3));

        mx = fmaxf(mx, fmaxf(fmaxf(v.x, v.y), fmaxf(v.z, v.w)));
        mn = fminf(mn, fminf(fminf(v.x, v.y), fminf(v.z, v.w)));

        unsigned u0 = __float_as_uint(v.x), u1 = __float_as_uint(v.y);
        unsigned u2 = __float_as_uint(v.z), u3 = __float_as_uint(v.w);
        unsigned nu0 = __shfl_down_sync(0xffffffffu, u0, 1);
        zc += (int)(((u0 ^ u1) >> 31) + ((u1 ^ u2) >> 31) + ((u2 ^ u3) >> 31)
                    + (((u3 ^ nu0) >> 31) & vmask));
    }

    float s1 = hsum2(s1p), s2 = hsum2(s2p), sa = hsum2(sap);

    s1 = warp_sum(s1); s2 = warp_sum(s2); sa = warp_sum(sa); sq = warp_sum(sq);
    mx = warp_max(mx); mn = warp_min(mn); zc = warp_sumi(zc);
    if (lane == 0) {
        w_a[wid] = s1; w_b[wid] = s2; w_c[wid] = sa; w_d[wid] = sq;
        w_mx[wid] = mx; w_mn[wid] = mn; w_i[wid] = zc;
    }
    __syncthreads();
    if (wid == 0) {
        bool ok = lane < NWARP;
        float r1 = ok ? w_a[lane] : 0.f, r2 = ok ? w_b[lane] : 0.f;
        float r3 = ok ? w_c[lane] : 0.f, r4 = ok ? w_d[lane] : 0.f;
        float rmx = ok ? w_mx[lane] : -INFINITY, rmn = ok ? w_mn[lane] : INFINITY;
        int rzc = ok ? w_i[lane] : 0;
        r1 = warp_sum(r1); r2 = warp_sum(r2); r3 = warp_sum(r3); r4 = warp_sum(r4);
        rmx = warp_max(rmx); rmn = warp_min(rmn); rzc = warp_sumi(rzc);
        if (lane == 0) {
            s_res[0] = r1; s_res[1] = r2; s_res[2] = r3; s_res[3] = r4;
            s_res[4] = rmx; s_res[5] = rmn;
            s_zc = rzc;
            s_mean = (float)((double)r1 * (1.0 / (double)TLEN));
        }
    }
    __syncthreads();

    const float mean = s_mean;
    const u64 nm2 = pk2(-mean, -mean);

    // ---------------- pass 2: centered moments + mean crossings (L2), branch-free ----------------
    u64 d2p = 0, d3p = 0, d4p = 0;
    int mc = 0;

#pragma unroll 8
    for (int k = tid; k < CHUNKS; k += THREADS) {
        float4 v = x4[k];
        u64 plo = pk2(v.x, v.y), phi = pk2(v.z, v.w);
        u64 dlo = add2(plo, nm2), dhi = add2(phi, nm2);
        u64 tlo = mul2(dlo, dlo), thi = mul2(dhi, dhi);

        d2p = add2(d2p, add2(tlo, thi));
        d3p = fma2(tlo, dlo, d3p);
        d3p = fma2(thi, dhi, d3p);
        d4p = fma2(tlo, tlo, d4p);
        d4p = fma2(thi, thi, d4p);

        float d0, d1, d2v, d3v;
        up2(dlo, d0, d1); up2(dhi, d2v, d3v);
        unsigned u0 = __float_as_uint(d0), u1 = __float_as_uint(d1);
        unsigned u2 = __float_as_uint(d2v), u3 = __float_as_uint(d3v);
        unsigned nu0 = __shfl_down_sync(0xffffffffu, u0, 1);
        mc += (int)(((u0 ^ u1) >> 31) + ((u1 ^ u2) >> 31) + ((u2 ^ u3) >> 31)
                    + (((u3 ^ nu0) >> 31) & vmask));
    }

    // ---------------- cleanup: 511 warp-span boundary pairs (both zcr & mcr) ----------------
    // Warp span j covers elements [128j, 128j+128); missing pair = (128j+127, 128j+128).
    int zce = 0;
    if (tid < 511) {
        float a = __ldg(xr + 128 * tid + 127);
        float b = __ldg(xr + 128 * tid + 128);
        zce = (int)(((__float_as_uint(a) ^ __float_as_uint(b)) >> 31));
        float ca = a - mean, cb = b - mean;
        mc += (int)(((__float_as_uint(ca) ^ __float_as_uint(cb)) >> 31));
    }

    float d2 = hsum2(d2p), d3 = hsum2(d3p), d4 = hsum2(d4p);
    d2 = warp_sum(d2); d3 = warp_sum(d3); d4 = warp_sum(d4);
    mc = warp_sumi(mc); zce = warp_sumi(zce);
    if (lane == 0) { w_a[wid] = d2; w_b[wid] = d3; w_c[wid] = d4; w_i[wid] = mc; w_j[wid] = zce; }
    __syncthreads();

    if (tid == 0) {
        double D2 = 0.0, D3 = 0.0, D4 = 0.0;
        int rmc = 0, rzce = 0;
        for (int i = 0; i < NWARP; i++) {
            D2 += (double)w_a[i]; D3 += (double)w_b[i]; D4 += (double)w_c[i];
            rmc += w_i[i]; rzce += w_j[i];
        }

        const double Td   = (double)TLEN;
        const double invT = 1.0 / Td;
        double S1 = s_res[0], S2 = s_res[1], Sa = s_res[2], Sq = s_res[3];
        double pk = s_res[4], pkn = s_res[5];
        int    zct = s_zc + rzce;

        double meanv     = S1 * invT;
        double var       = D2 / (Td - 1.0);
        double stdv      = sqrt(var);
        double sq_mean   = S2 * invT;
        double rms       = sqrt(sq_mean);
        double ptp       = pk - pkn;
        double abs_peak  = fabs(pk);
        double crest     = abs_peak / (rms + EPSV);
        double mean_abs  = Sa * invT;
        double shape     = rms / (mean_abs + EPSV);
        double impulse   = abs_peak / (mean_abs + EPSV);
        double sqrt_mean = Sq * invT;
        double clearance = abs_peak / (sqrt_mean * sqrt_mean + EPSV);
        double skew      = (D3 * invT) / (stdv * stdv * stdv + EPSV);
        double kurt      = (D4 * invT) / (var * var + EPSV) - 3.0;
        double zcr       = (double)zct / (Td - 1.0);
        double mcr       = (double)rmc / (Td - 1.0);
        double margin    = abs_peak / (sqrt_mean + EPSV);
        double energy    = S2;

        float* o = out + (size_t)row * 17;
        o[0]  = (float)meanv;
        o[1]  = (float)stdv;
        o[2]  = (float)var;
        o[3]  = (float)rms;
        o[4]  = (float)pk;
        o[5]  = (float)pkn;
        o[6]  = (float)ptp;
        o[7]  = (float)crest;
        o[8]  = (float)shape;
        o[9]  = (float)impulse;
        o[10] = (float)clearance;
        o[11] = (float)skew;
        o[12] = (float)kurt;
        o[13] = (float)zcr;
        o[14] = (float)mcr;
        o[15] = (float)margin;
        o[16] = (float)energy;
    }
}

extern "C" void kernel_launch(void* const* d_in, const int* in_sizes, int n_in,
                              void* d_out, int out_size) {
    const float* x = (const float*)d_in[0];
    float* out = (float*)d_out;
    int rows = in_sizes[0] / TLEN;   // 64*16 = 1024
    stat_feat_kernel<<<rows, THREADS>>>(x, out);
}